// round 15
// baseline (speedup 1.0000x reference)
#include <cuda_runtime.h>

#define IMG    512
#define OUTD   502
#define NIMG   96
#define TILE_W 86
#define VCOLS  96
#define TILE_H 16
#define GBX    6
#define GBY    32
#define NBLK   (GBX * GBY * NIMG)   // 18432
#define SROW   104                   // bank-conflict-free (u64 planes; verified mod 16)
#define G      11                    // phase-2 outputs per thread

// Gaussian(sigma=1.5, K=11) normalized weights
#define W0 0.00102839f
#define W1 0.00759864f
#define W2 0.03600077f
#define W3 0.10936070f
#define W4 0.21300553f
#define W5 0.26601172f

// SSIM constants for the 4 possible dynamic ranges L = maxv - minv
// combo index = 2*flag_max + flag_min;  L: 1, 2, 255, 256
#define C1_0 1.0e-4f
#define C2_0 9.0e-4f
#define C1_1 4.0e-4f
#define C2_1 3.6e-3f
#define C1_2 6.5025f
#define C2_2 58.5225f
#define C1_3 6.5536f
#define C2_3 58.9824f

typedef unsigned long long u64;

#define PACK2(out, lo, hi) asm("mov.b64 %0, {%1, %2};" : "=l"(out) : "f"(lo), "f"(hi))
#define UNPACK2(lo, hi, in) asm("mov.b64 {%0, %1}, %2;" : "=f"(lo), "=f"(hi) : "l"(in))
#define FMA2(d, a, b, c) asm("fma.rn.f32x2 %0, %1, %2, %3;" : "=l"(d) : "l"(a), "l"(b), "l"(c))
#define MUL2(d, a, b)    asm("mul.rn.f32x2 %0, %1, %2;" : "=l"(d) : "l"(a), "l"(b))

#define WIDX(k) ((k) < 6 ? (k) : 10 - (k))

__device__ int      g_flags[2] = {0, 0};
__device__ unsigned g_count    = 0u;
__device__ float4   g_partials[NBLK];   // per-block sums for the 4 (C1,C2) combos

// phase-1 vertical conv body; ROWGUARD selects per-row bounds checking.
// Also tracks min/max of img1 values for the dynamic-range flags.
template <bool ROWGUARD>
__device__ __forceinline__ void vconv(const float* __restrict__ p1,
                                      const float* __restrict__ p2,
                                      int ybase, int gx, bool colok,
                                      const u64* w2,
                                      u64 (*s01)[SROW], u64 (*sq)[SROW], int tid,
                                      float& amax, float& amin) {
    u64 acc01[11], accq[11];

#pragma unroll
    for (int j = 0; j < TILE_H + 10; j++) {
        const int yin = ybase + j;
        float a = 0.0f, b = 0.0f;
        if (colok && (!ROWGUARD || yin < IMG)) {
            a = p1[yin * IMG + gx];
            b = p2[yin * IMG + gx];
        }
        amax = fmaxf(amax, a);           // zero-filled lanes contribute 0: flag-neutral
        amin = fminf(amin, a);
        const float ab   = a * b;
        const float aabb = fmaf(a, a, b * b);
        u64 vab, vq;
        PACK2(vab, a, b);
        PACK2(vq, aabb, ab);

        // input row j feeds output rows r in [j-10, j] ∩ [0, TILE_H-1]
#pragma unroll
        for (int r = 0; r < TILE_H; r++) {
            const int k = j - r;
            if (k > 0 && k < 11) {
                const int m = r % 11;                  // static after unroll
                const u64 w = w2[WIDX(k)];
                FMA2(acc01[m], vab, w, acc01[m]);
                FMA2(accq[m],  vq,  w, accq[m]);
            } else if (k == 0) {                       // first tap: overwrite (no zero-init)
                const int m = r % 11;
                MUL2(acc01[m], vab, w2[0]);
                MUL2(accq[m],  vq,  w2[0]);
            }
        }

        if (j >= 10) {                                 // output row j-10 complete
            const int r = j - 10;
            const int m = r % 11;
            s01[r][tid] = acc01[m];
            sq [r][tid] = accq[m];
        }
    }
}

__global__ __launch_bounds__(128, 6)
void k_ssim(const float* __restrict__ img1, const float* __restrict__ img2,
            float* __restrict__ out) {
    __shared__ u64   s01[TILE_H][SROW];   // packed (vconv a, vconv b)
    __shared__ u64   sq [TILE_H][SROW];   // packed (vconv a^2+b^2, vconv a*b)
    __shared__ float warpsum[4][4];       // [warp][combo]
    __shared__ int   sf[2];               // block-local flags
    __shared__ int   s_last;
    __shared__ double red[4];

    u64 w2[6];
    {
        const float wv[6] = {W0, W1, W2, W3, W4, W5};
#pragma unroll
        for (int k = 0; k < 6; k++) PACK2(w2[k], wv[k], wv[k]);
    }

    const int tid = threadIdx.x;
    if (tid < 2) sf[tid] = 0;
    const int bx = blockIdx.x, by = blockIdx.y, z = blockIdx.z;
    const float* p1 = img1 + (size_t)z * IMG * IMG;
    const float* p2 = img2 + (size_t)z * IMG * IMG;
    const int ybase = by * TILE_H;

    // ---------------- Phase 1: vertical conv + img1 range scan ----------------------------
    float amax = 0.0f, amin = 0.0f;
    if (tid < VCOLS) {
        const int gx = bx * TILE_W + tid;
        const bool colok = (gx < IMG);
        if (ybase + TILE_H + 10 <= IMG) {              // uniform: true for by < 31
            vconv<false>(p1, p2, ybase, gx, colok, w2, s01, sq, tid, amax, amin);
        } else {
            vconv<true>(p1, p2, ybase, gx, colok, w2, s01, sq, tid, amax, amin);
        }
    }
    __syncthreads();

    // block-local flag aggregation (rare path: no atomics when flags are false)
    {
        unsigned b1 = __ballot_sync(0xffffffffu, amax > 128.0f);
        unsigned b2 = __ballot_sync(0xffffffffu, amin < -0.5f);
        if ((tid & 31) == 0) {
            if (b1) atomicOr(&sf[0], 1);
            if (b2) atomicOr(&sf[1], 1);
        }
    }

    // ---------------- Phase 2: horizontal 11-tap conv, 11 outputs per thread --------------
    const int y  = tid >> 3;      // 0..15 output row
    const int cg = tid & 7;       // 0..7  column group
    const int xs = cg * G;        // local out cols xs..xs+10 (reads to xs+20 <= 97 < SROW)

    u64 o01[G], oq[G];
#pragma unroll
    for (int s = 0; s < G; s++) { o01[s] = 0ull; oq[s] = 0ull; }

    {
        const u64* r01 = &s01[y][xs];
#pragma unroll
        for (int i = 0; i < 21; i++) {
            const u64 v = r01[i];
#pragma unroll
            for (int s = 0; s < G; s++) {
                const int k = i - s;
                if (k >= 0 && k < 11) FMA2(o01[s], v, w2[WIDX(k)], o01[s]);
            }
        }
    }
    {
        const u64* rq = &sq[y][xs];
#pragma unroll
        for (int i = 0; i < 21; i++) {
            const u64 v = rq[i];
#pragma unroll
            for (int s = 0; s < G; s++) {
                const int k = i - s;
                if (k >= 0 && k < 11) FMA2(oq[s], v, w2[WIDX(k)], oq[s]);
            }
        }
    }

    // ---------------- SSIM map for all 4 (C1,C2) combos + block-local sums ----------------
    const int gy   = ybase + y;
    const int xlim = min(TILE_W, OUTD - bx * TILE_W);

    float ls0 = 0.0f, ls1 = 0.0f, ls2 = 0.0f, ls3 = 0.0f;
    if (gy < OUTD) {
#pragma unroll
        for (int s = 0; s < G; s++) {
            const int x = xs + s;
            if (x < xlim) {
                float mu1, mu2, spp, sab;
                UNPACK2(mu1, mu2, o01[s]);
                UNPACK2(spp, sab, oq[s]);
                const float mu1s  = mu1 * mu1, mu2s = mu2 * mu2, mu12 = mu1 * mu2;
                const float musum = mu1s + mu2s;
                const float sigsum = spp - musum;          // sigma1_sq + sigma2_sq
                const float sig12  = sab - mu12;           // sigma12
                const float n1 = 2.0f * mu12, n2 = 2.0f * sig12;
                ls0 += __fdividef((n1 + C1_0) * (n2 + C2_0), (musum + C1_0) * (sigsum + C2_0));
                ls1 += __fdividef((n1 + C1_1) * (n2 + C2_1), (musum + C1_1) * (sigsum + C2_1));
                ls2 += __fdividef((n1 + C1_2) * (n2 + C2_2), (musum + C1_2) * (sigsum + C2_2));
                ls3 += __fdividef((n1 + C1_3) * (n2 + C2_3), (musum + C1_3) * (sigsum + C2_3));
            }
        }
    }

#pragma unroll
    for (int off = 16; off > 0; off >>= 1) {
        ls0 += __shfl_down_sync(0xffffffffu, ls0, off);
        ls1 += __shfl_down_sync(0xffffffffu, ls1, off);
        ls2 += __shfl_down_sync(0xffffffffu, ls2, off);
        ls3 += __shfl_down_sync(0xffffffffu, ls3, off);
    }

    if ((tid & 31) == 0) {
        warpsum[tid >> 5][0] = ls0;
        warpsum[tid >> 5][1] = ls1;
        warpsum[tid >> 5][2] = ls2;
        warpsum[tid >> 5][3] = ls3;
    }
    __syncthreads();

    const int bid = bx + GBX * (by + GBY * z);
    if (tid == 0) {
        float4 p;
        p.x = warpsum[0][0] + warpsum[1][0] + warpsum[2][0] + warpsum[3][0];
        p.y = warpsum[0][1] + warpsum[1][1] + warpsum[2][1] + warpsum[3][1];
        p.z = warpsum[0][2] + warpsum[1][2] + warpsum[2][2] + warpsum[3][2];
        p.w = warpsum[0][3] + warpsum[1][3] + warpsum[2][3] + warpsum[3][3];
        g_partials[bid] = p;
        if (sf[0]) atomicOr(&g_flags[0], 1);
        if (sf[1]) atomicOr(&g_flags[1], 1);
        __threadfence();
        unsigned v = atomicAdd(&g_count, 1u);
        s_last = (v == NBLK - 1) ? 1 : 0;
    }
    __syncthreads();

    // ---------------- last block: select combo, final reduction, state reset --------------
    if (s_last) {
        const int combo = (g_flags[0] ? 2 : 0) + (g_flags[1] ? 1 : 0);
        const float* base = (const float*)g_partials + combo;
        double s = 0.0;
        const int per = NBLK / 128;  // 144
#pragma unroll 4
        for (int i = 0; i < per; i++)
            s += (double)__ldcg(&base[4 * (tid * per + i)]);
#pragma unroll
        for (int off = 16; off > 0; off >>= 1)
            s += __shfl_down_sync(0xffffffffu, s, off);
        if ((tid & 31) == 0) red[tid >> 5] = s;
        __syncthreads();
        if (tid == 0) {
            const double cnt = (double)NIMG * OUTD * OUTD;
            out[0] = (float)(1.0 - (red[0] + red[1] + red[2] + red[3]) / cnt);
            g_flags[0] = 0;
            g_flags[1] = 0;
            g_count    = 0u;
        }
    }
}

extern "C" void kernel_launch(void* const* d_in, const int* in_sizes, int n_in,
                              void* d_out, int out_size) {
    const float* img1 = (const float*)d_in[0];
    const float* img2 = (const float*)d_in[1];
    float* out = (float*)d_out;

    dim3 grid(GBX, GBY, NIMG);
    k_ssim<<<grid, 128>>>(img1, img2, out);
}

// round 16
// speedup vs baseline: 1.1714x; 1.1714x over previous
#include <cuda_runtime.h>

#define IMG    512
#define OUTD   502
#define NIMG   96
#define TILE_W 86
#define VCOLS  96
#define TILE_H 16
#define GBX    6
#define GBY    32
#define NBLK   (GBX * GBY * NIMG)   // 18432
#define SROW   104                   // bank-conflict-free (u64 planes; verified mod 16)
#define G      11                    // phase-2 outputs per thread

// k_flags exact partition
#define FB     3072
#define FT     256
#define FITER  8                     // 3072*256*8 = 6291456 = 96*512*512/4

// Gaussian(sigma=1.5, K=11) normalized weights
#define W0 0.00102839f
#define W1 0.00759864f
#define W2 0.03600077f
#define W3 0.10936070f
#define W4 0.21300553f
#define W5 0.26601172f

typedef unsigned long long u64;

#define PACK2(out, lo, hi) asm("mov.b64 %0, {%1, %2};" : "=l"(out) : "f"(lo), "f"(hi))
#define UNPACK2(lo, hi, in) asm("mov.b64 {%0, %1}, %2;" : "=f"(lo), "=f"(hi) : "l"(in))
#define FMA2(d, a, b, c) asm("fma.rn.f32x2 %0, %1, %2, %3;" : "=l"(d) : "l"(a), "l"(b), "l"(c))
#define MUL2(d, a, b)    asm("mul.rn.f32x2 %0, %1, %2;" : "=l"(d) : "l"(a), "l"(b))

#define WIDX(k) ((k) < 6 ? (k) : 10 - (k))

__device__ int      g_flags[2] = {0, 0};
__device__ unsigned g_count    = 0u;
__device__ float    g_partials[NBLK];

// any(img1 > 128), any(img1 < -0.5); exact partition, 8 independent loads/thread
__global__ __launch_bounds__(FT)
void k_flags(const float4* __restrict__ x) {
    const int base = blockIdx.x * FT + threadIdx.x;
    bool f1 = false, f2 = false;
#pragma unroll
    for (int i = 0; i < FITER; i++) {
        float4 v = x[base + i * (FB * FT)];
        f1 |= (v.x > 128.0f) | (v.y > 128.0f) | (v.z > 128.0f) | (v.w > 128.0f);
        f2 |= (v.x < -0.5f) | (v.y < -0.5f) | (v.z < -0.5f) | (v.w < -0.5f);
    }
    unsigned m1 = __ballot_sync(0xffffffffu, f1);
    unsigned m2 = __ballot_sync(0xffffffffu, f2);
    if ((threadIdx.x & 31) == 0) {
        if (m1) atomicOr(&g_flags[0], 1);
        if (m2) atomicOr(&g_flags[1], 1);
    }
}

// phase-1 vertical conv body; ROWGUARD selects per-row bounds checking
template <bool ROWGUARD>
__device__ __forceinline__ void vconv(const float* __restrict__ p1,
                                      const float* __restrict__ p2,
                                      int ybase, int gx, bool colok,
                                      const u64* w2,
                                      u64 (*s01)[SROW], u64 (*sq)[SROW], int tid) {
    u64 acc01[11], accq[11];

#pragma unroll
    for (int j = 0; j < TILE_H + 10; j++) {
        const int yin = ybase + j;
        float a = 0.0f, b = 0.0f;
        if (colok && (!ROWGUARD || yin < IMG)) {
            a = p1[yin * IMG + gx];
            b = p2[yin * IMG + gx];
        }
        const float ab   = a * b;
        const float aabb = fmaf(a, a, b * b);
        u64 vab, vq;
        PACK2(vab, a, b);
        PACK2(vq, aabb, ab);

        // input row j feeds output rows r in [j-10, j] ∩ [0, TILE_H-1]
#pragma unroll
        for (int r = 0; r < TILE_H; r++) {
            const int k = j - r;
            if (k > 0 && k < 11) {
                const int m = r % 11;                  // static after unroll
                const u64 w = w2[WIDX(k)];
                FMA2(acc01[m], vab, w, acc01[m]);
                FMA2(accq[m],  vq,  w, accq[m]);
            } else if (k == 0) {                       // first tap: overwrite (no zero-init)
                const int m = r % 11;
                MUL2(acc01[m], vab, w2[0]);
                MUL2(accq[m],  vq,  w2[0]);
            }
        }

        if (j >= 10) {                                 // output row j-10 complete
            const int r = j - 10;
            const int m = r % 11;
            s01[r][tid] = acc01[m];
            sq [r][tid] = accq[m];
        }
    }
}

__global__ __launch_bounds__(128, 7)
void k_ssim(const float* __restrict__ img1, const float* __restrict__ img2,
            float* __restrict__ out) {
    __shared__ u64   s01[TILE_H][SROW];   // packed (vconv a, vconv b)
    __shared__ u64   sq [TILE_H][SROW];   // packed (vconv a^2+b^2, vconv a*b)
    __shared__ float warpsum[4];
    __shared__ int   s_last;
    __shared__ double red[4];

    u64 w2[6];
    {
        const float wv[6] = {W0, W1, W2, W3, W4, W5};
#pragma unroll
        for (int k = 0; k < 6; k++) PACK2(w2[k], wv[k], wv[k]);
    }

    const int tid = threadIdx.x;
    const int bx = blockIdx.x, by = blockIdx.y, z = blockIdx.z;
    const float* p1 = img1 + (size_t)z * IMG * IMG;
    const float* p2 = img2 + (size_t)z * IMG * IMG;
    const int ybase = by * TILE_H;

    // ---------------- Phase 1: vertical conv (warps 0-2; warp 3 skips) --------------------
    if (tid < VCOLS) {
        const int gx = bx * TILE_W + tid;
        const bool colok = (gx < IMG);
        if (ybase + TILE_H + 10 <= IMG) {              // uniform: true for by < 31
            vconv<false>(p1, p2, ybase, gx, colok, w2, s01, sq, tid);
        } else {
            vconv<true>(p1, p2, ybase, gx, colok, w2, s01, sq, tid);
        }
    }
    __syncthreads();

    // ---------------- Phase 2: horizontal 11-tap conv, 11 outputs per thread --------------
    // first tap (k==0, i==s) overwrites via MUL2: no zero-init of accumulators
    const int y  = tid >> 3;      // 0..15 output row
    const int cg = tid & 7;       // 0..7  column group
    const int xs = cg * G;        // local out cols xs..xs+10 (reads to xs+20 <= 97 < SROW)

    u64 o01[G], oq[G];

    {
        const u64* r01 = &s01[y][xs];
#pragma unroll
        for (int i = 0; i < 21; i++) {
            const u64 v = r01[i];
#pragma unroll
            for (int s = 0; s < G; s++) {
                const int k = i - s;
                if (k == 0) {
                    MUL2(o01[s], v, w2[0]);
                } else if (k > 0 && k < 11) {
                    FMA2(o01[s], v, w2[WIDX(k)], o01[s]);
                }
            }
        }
    }
    {
        const u64* rq = &sq[y][xs];
#pragma unroll
        for (int i = 0; i < 21; i++) {
            const u64 v = rq[i];
#pragma unroll
            for (int s = 0; s < G; s++) {
                const int k = i - s;
                if (k == 0) {
                    MUL2(oq[s], v, w2[0]);
                } else if (k > 0 && k < 11) {
                    FMA2(oq[s], v, w2[WIDX(k)], oq[s]);
                }
            }
        }
    }

    // ---------------- SSIM map + block-local sum ----------------
    const float maxv = g_flags[0] ? 255.0f : 1.0f;
    const float minv = g_flags[1] ? -1.0f : 0.0f;
    const float L  = maxv - minv;
    const float C1 = (0.01f * L) * (0.01f * L);
    const float C2 = (0.03f * L) * (0.03f * L);

    float lsum = 0.0f;
    if (by < GBY - 1 && bx < GBX - 1) {
        // interior block: gy = ybase+y <= 480+15 < 502 and x <= 85 < xlim=86 always
#pragma unroll
        for (int s = 0; s < G; s++) {
            float mu1, mu2, spp, sab;
            UNPACK2(mu1, mu2, o01[s]);
            UNPACK2(spp, sab, oq[s]);
            const float mu1s = mu1 * mu1, mu2s = mu2 * mu2, mu12 = mu1 * mu2;
            const float sigsum = spp - mu1s - mu2s;
            const float sig12  = sab - mu12;
            const float num = (2.0f * mu12 + C1) * (2.0f * sig12 + C2);
            const float den = (mu1s + mu2s + C1) * (sigsum + C2);
            lsum += __fdividef(num, den);
        }
    } else {
        const int gy   = ybase + y;
        const int xlim = min(TILE_W, OUTD - bx * TILE_W);
        if (gy < OUTD) {
#pragma unroll
            for (int s = 0; s < G; s++) {
                const int x = xs + s;
                if (x < xlim) {
                    float mu1, mu2, spp, sab;
                    UNPACK2(mu1, mu2, o01[s]);
                    UNPACK2(spp, sab, oq[s]);
                    const float mu1s = mu1 * mu1, mu2s = mu2 * mu2, mu12 = mu1 * mu2;
                    const float sigsum = spp - mu1s - mu2s;
                    const float sig12  = sab - mu12;
                    const float num = (2.0f * mu12 + C1) * (2.0f * sig12 + C2);
                    const float den = (mu1s + mu2s + C1) * (sigsum + C2);
                    lsum += __fdividef(num, den);
                }
            }
        }
    }

#pragma unroll
    for (int off = 16; off > 0; off >>= 1)
        lsum += __shfl_down_sync(0xffffffffu, lsum, off);

    if ((tid & 31) == 0) warpsum[tid >> 5] = lsum;
    __syncthreads();

    const int bid = bx + GBX * (by + GBY * z);
    if (tid == 0) {
        g_partials[bid] = warpsum[0] + warpsum[1] + warpsum[2] + warpsum[3];
        __threadfence();
        unsigned v = atomicAdd(&g_count, 1u);
        s_last = (v == NBLK - 1) ? 1 : 0;
    }
    __syncthreads();

    // ---------------- last block: final reduction + state reset ----------------
    if (s_last) {
        double s = 0.0;
        const int per = NBLK / 128;  // 144
#pragma unroll 4
        for (int i = 0; i < per; i++)
            s += (double)__ldcg(&g_partials[tid * per + i]);
#pragma unroll
        for (int off = 16; off > 0; off >>= 1)
            s += __shfl_down_sync(0xffffffffu, s, off);
        if ((tid & 31) == 0) red[tid >> 5] = s;
        __syncthreads();
        if (tid == 0) {
            const double cnt = (double)NIMG * OUTD * OUTD;
            out[0] = (float)(1.0 - (red[0] + red[1] + red[2] + red[3]) / cnt);
            g_flags[0] = 0;
            g_flags[1] = 0;
            g_count    = 0u;
        }
    }
}

extern "C" void kernel_launch(void* const* d_in, const int* in_sizes, int n_in,
                              void* d_out, int out_size) {
    const float* img1 = (const float*)d_in[0];
    const float* img2 = (const float*)d_in[1];
    float* out = (float*)d_out;

    k_flags<<<FB, FT>>>((const float4*)img1);
    dim3 grid(GBX, GBY, NIMG);
    k_ssim<<<grid, 128>>>(img1, img2, out);
}

// round 17
// speedup vs baseline: 1.1716x; 1.0002x over previous
#include <cuda_runtime.h>

#define IMG    512
#define OUTD   502
#define NIMG   96
#define TILE_W 86
#define VCOLS  96
#define TILE_H 16
#define GBX    6
#define GBY    32
#define NBLK   (GBX * GBY * NIMG)   // 18432
#define SROW   104                   // bank-conflict-free (u64 planes; verified mod 16)
#define G      11                    // phase-2 outputs per thread

// k_flags exact partition
#define FB     3072
#define FT     256
#define FITER  8                     // 3072*256*8 = 6291456 = 96*512*512/4

// Gaussian(sigma=1.5, K=11) normalized weights
#define W0 0.00102839f
#define W1 0.00759864f
#define W2 0.03600077f
#define W3 0.10936070f
#define W4 0.21300553f
#define W5 0.26601172f

typedef unsigned long long u64;

#define PACK2(out, lo, hi) asm("mov.b64 %0, {%1, %2};" : "=l"(out) : "f"(lo), "f"(hi))
#define UNPACK2(lo, hi, in) asm("mov.b64 {%0, %1}, %2;" : "=f"(lo), "=f"(hi) : "l"(in))
#define FMA2(d, a, b, c) asm("fma.rn.f32x2 %0, %1, %2, %3;" : "=l"(d) : "l"(a), "l"(b), "l"(c))
#define MUL2(d, a, b)    asm("mul.rn.f32x2 %0, %1, %2;" : "=l"(d) : "l"(a), "l"(b))

#define WIDX(k) ((k) < 6 ? (k) : 10 - (k))

__device__ int      g_flags[2] = {0, 0};
__device__ unsigned g_count    = 0u;
__device__ float    g_partials[NBLK];

// any(img1 > 128), any(img1 < -0.5); exact partition, 8 independent loads/thread
__global__ __launch_bounds__(FT)
void k_flags(const float4* __restrict__ x) {
    const int base = blockIdx.x * FT + threadIdx.x;
    bool f1 = false, f2 = false;
#pragma unroll
    for (int i = 0; i < FITER; i++) {
        float4 v = x[base + i * (FB * FT)];
        f1 |= (v.x > 128.0f) | (v.y > 128.0f) | (v.z > 128.0f) | (v.w > 128.0f);
        f2 |= (v.x < -0.5f) | (v.y < -0.5f) | (v.z < -0.5f) | (v.w < -0.5f);
    }
    unsigned m1 = __ballot_sync(0xffffffffu, f1);
    unsigned m2 = __ballot_sync(0xffffffffu, f2);
    if ((threadIdx.x & 31) == 0) {
        if (m1) atomicOr(&g_flags[0], 1);
        if (m2) atomicOr(&g_flags[1], 1);
    }
}

// phase-1 vertical conv body; ROWGUARD selects per-row bounds checking
template <bool ROWGUARD>
__device__ __forceinline__ void vconv(const float* __restrict__ p1,
                                      const float* __restrict__ p2,
                                      int ybase, int gx, bool colok,
                                      const u64* w2,
                                      u64 (*s01)[SROW], u64 (*sq)[SROW], int tid) {
    u64 acc01[11], accq[11];

#pragma unroll
    for (int j = 0; j < TILE_H + 10; j++) {
        const int yin = ybase + j;
        float a = 0.0f, b = 0.0f;
        if (colok && (!ROWGUARD || yin < IMG)) {
            a = p1[yin * IMG + gx];
            b = p2[yin * IMG + gx];
        }
        const float ab   = a * b;
        const float aabb = fmaf(a, a, b * b);
        u64 vab, vq;
        PACK2(vab, a, b);
        PACK2(vq, aabb, ab);

        // input row j feeds output rows r in [j-10, j] ∩ [0, TILE_H-1]
#pragma unroll
        for (int r = 0; r < TILE_H; r++) {
            const int k = j - r;
            if (k > 0 && k < 11) {
                const int m = r % 11;                  // static after unroll
                const u64 w = w2[WIDX(k)];
                FMA2(acc01[m], vab, w, acc01[m]);
                FMA2(accq[m],  vq,  w, accq[m]);
            } else if (k == 0) {                       // first tap: overwrite (no zero-init)
                const int m = r % 11;
                MUL2(acc01[m], vab, w2[0]);
                MUL2(accq[m],  vq,  w2[0]);
            }
        }

        if (j >= 10) {                                 // output row j-10 complete
            const int r = j - 10;
            const int m = r % 11;
            s01[r][tid] = acc01[m];
            sq [r][tid] = accq[m];
        }
    }
}

__global__ __launch_bounds__(128, 7)
void k_ssim(const float* __restrict__ img1, const float* __restrict__ img2,
            float* __restrict__ out) {
    __shared__ u64   s01[TILE_H][SROW];   // packed (vconv a, vconv b)
    __shared__ u64   sq [TILE_H][SROW];   // packed (vconv a^2+b^2, vconv a*b)
    __shared__ float warpsum[4];
    __shared__ int   s_last;
    __shared__ double red[4];

    u64 w2[6];
    {
        const float wv[6] = {W0, W1, W2, W3, W4, W5};
#pragma unroll
        for (int k = 0; k < 6; k++) PACK2(w2[k], wv[k], wv[k]);
    }

    const int tid = threadIdx.x;
    const int bx = blockIdx.x, by = blockIdx.y, z = blockIdx.z;
    const float* p1 = img1 + (size_t)z * IMG * IMG;
    const float* p2 = img2 + (size_t)z * IMG * IMG;
    const int ybase = by * TILE_H;

    // ---------------- Phase 1: vertical conv (warps 0-2; warp 3 skips) --------------------
    if (tid < VCOLS) {
        const int gx = bx * TILE_W + tid;
        const bool colok = (gx < IMG);
        if (ybase + TILE_H + 10 <= IMG) {              // uniform: true for by < 31
            vconv<false>(p1, p2, ybase, gx, colok, w2, s01, sq, tid);
        } else {
            vconv<true>(p1, p2, ybase, gx, colok, w2, s01, sq, tid);
        }
    }
    __syncthreads();

    // ---------------- Phase 2: horizontal 11-tap conv, 11 outputs per thread --------------
    // first tap (k==0, i==s) overwrites via MUL2: no zero-init of accumulators
    const int y  = tid >> 3;      // 0..15 output row
    const int cg = tid & 7;       // 0..7  column group
    const int xs = cg * G;        // local out cols xs..xs+10 (reads to xs+20 <= 97 < SROW)

    u64 o01[G], oq[G];

    {
        const u64* r01 = &s01[y][xs];
#pragma unroll
        for (int i = 0; i < 21; i++) {
            const u64 v = r01[i];
#pragma unroll
            for (int s = 0; s < G; s++) {
                const int k = i - s;
                if (k == 0) {
                    MUL2(o01[s], v, w2[0]);
                } else if (k > 0 && k < 11) {
                    FMA2(o01[s], v, w2[WIDX(k)], o01[s]);
                }
            }
        }
    }
    {
        const u64* rq = &sq[y][xs];
#pragma unroll
        for (int i = 0; i < 21; i++) {
            const u64 v = rq[i];
#pragma unroll
            for (int s = 0; s < G; s++) {
                const int k = i - s;
                if (k == 0) {
                    MUL2(oq[s], v, w2[0]);
                } else if (k > 0 && k < 11) {
                    FMA2(oq[s], v, w2[WIDX(k)], oq[s]);
                }
            }
        }
    }

    // ---------------- SSIM map + block-local sum ----------------
    const float maxv = g_flags[0] ? 255.0f : 1.0f;
    const float minv = g_flags[1] ? -1.0f : 0.0f;
    const float L  = maxv - minv;
    const float C1 = (0.01f * L) * (0.01f * L);
    const float C2 = (0.03f * L) * (0.03f * L);

    float lsum = 0.0f;
    if (by < GBY - 1 && bx < GBX - 1) {
        // interior block: gy <= 495 < 502 always; x guard is the compile-time TILE_W
        // (cg=7 lanes own only 9 of 11 outputs: xs+s must stay < 86)
#pragma unroll
        for (int s = 0; s < G; s++) {
            const int x = xs + s;
            if (x < TILE_W) {
                float mu1, mu2, spp, sab;
                UNPACK2(mu1, mu2, o01[s]);
                UNPACK2(spp, sab, oq[s]);
                const float mu1s = mu1 * mu1, mu2s = mu2 * mu2, mu12 = mu1 * mu2;
                const float sigsum = spp - mu1s - mu2s;
                const float sig12  = sab - mu12;
                const float num = (2.0f * mu12 + C1) * (2.0f * sig12 + C2);
                const float den = (mu1s + mu2s + C1) * (sigsum + C2);
                lsum += __fdividef(num, den);
            }
        }
    } else {
        const int gy   = ybase + y;
        const int xlim = min(TILE_W, OUTD - bx * TILE_W);
        if (gy < OUTD) {
#pragma unroll
            for (int s = 0; s < G; s++) {
                const int x = xs + s;
                if (x < xlim) {
                    float mu1, mu2, spp, sab;
                    UNPACK2(mu1, mu2, o01[s]);
                    UNPACK2(spp, sab, oq[s]);
                    const float mu1s = mu1 * mu1, mu2s = mu2 * mu2, mu12 = mu1 * mu2;
                    const float sigsum = spp - mu1s - mu2s;
                    const float sig12  = sab - mu12;
                    const float num = (2.0f * mu12 + C1) * (2.0f * sig12 + C2);
                    const float den = (mu1s + mu2s + C1) * (sigsum + C2);
                    lsum += __fdividef(num, den);
                }
            }
        }
    }

#pragma unroll
    for (int off = 16; off > 0; off >>= 1)
        lsum += __shfl_down_sync(0xffffffffu, lsum, off);

    if ((tid & 31) == 0) warpsum[tid >> 5] = lsum;
    __syncthreads();

    const int bid = bx + GBX * (by + GBY * z);
    if (tid == 0) {
        g_partials[bid] = warpsum[0] + warpsum[1] + warpsum[2] + warpsum[3];
        __threadfence();
        unsigned v = atomicAdd(&g_count, 1u);
        s_last = (v == NBLK - 1) ? 1 : 0;
    }
    __syncthreads();

    // ---------------- last block: final reduction + state reset ----------------
    if (s_last) {
        double s = 0.0;
        const int per = NBLK / 128;  // 144
#pragma unroll 4
        for (int i = 0; i < per; i++)
            s += (double)__ldcg(&g_partials[tid * per + i]);
#pragma unroll
        for (int off = 16; off > 0; off >>= 1)
            s += __shfl_down_sync(0xffffffffu, s, off);
        if ((tid & 31) == 0) red[tid >> 5] = s;
        __syncthreads();
        if (tid == 0) {
            const double cnt = (double)NIMG * OUTD * OUTD;
            out[0] = (float)(1.0 - (red[0] + red[1] + red[2] + red[3]) / cnt);
            g_flags[0] = 0;
            g_flags[1] = 0;
            g_count    = 0u;
        }
    }
}

extern "C" void kernel_launch(void* const* d_in, const int* in_sizes, int n_in,
                              void* d_out, int out_size) {
    const float* img1 = (const float*)d_in[0];
    const float* img2 = (const float*)d_in[1];
    float* out = (float*)d_out;

    k_flags<<<FB, FT>>>((const float4*)img1);
    dim3 grid(GBX, GBY, NIMG);
    k_ssim<<<grid, 128>>>(img1, img2, out);
}